// round 1
// baseline (speedup 1.0000x reference)
#include <cuda_runtime.h>
#include <math.h>

#define TT 2048
#define HH 1024
#define II 1024
#define EE 16
#define KK 4
#define PP (TT*KK)
#define ALPHA 1.702f
#define LIMIT 7.0f
#define EPSV 1e-5f

// ---------------- scratch (device globals; no allocations allowed) ----------
__device__ float g_tnorm[TT*HH];          // 8 MB  normalized tokens (fp32)
__device__ int   g_cnt[EE];
__device__ int   g_base[EE];
__device__ int   g_cursor[EE];
__device__ int   g_slot_tok[PP];          // slot -> token
__device__ int   g_pair_slot[PP];         // (t,k) -> slot
__device__ int   g_topk_e[PP];
__device__ float g_topk_w[PP];
__device__ float g_act[(size_t)PP*II];    // 32 MB  swiglu activations
__device__ float g_ypair[(size_t)PP*HH];  // 32 MB  per-pair FFN output (no bias/weight)

// ---------------- packed f32x2 helpers (Blackwell FFMA2) --------------------
__device__ __forceinline__ unsigned long long pk2(float x, float y) {
    unsigned long long r;
    asm("mov.b64 %0, {%1, %2};" : "=l"(r) : "f"(x), "f"(y));
    return r;
}
__device__ __forceinline__ void fma2(unsigned long long& c, unsigned long long a, unsigned long long b) {
    asm("fma.rn.f32x2 %0, %1, %2, %0;" : "+l"(c) : "l"(a), "l"(b));
}
__device__ __forceinline__ float2 unpk(unsigned long long v) {
    float2 f;
    asm("mov.b64 {%0, %1}, %2;" : "=f"(f.x), "=f"(f.y) : "l"(v));
    return f;
}

// ---------------- kernel 0: zero expert counts ------------------------------
__global__ void k_zero() {
    if (threadIdx.x < EE) g_cnt[threadIdx.x] = 0;
}

// ---------------- kernel 1: rmsnorm + gate + top-4 + softmax ----------------
__global__ __launch_bounds__(256) void k_norm_gate(
    const float* __restrict__ x, const float* __restrict__ nscale,
    const float* __restrict__ gw, const float* __restrict__ gb)
{
    int t = blockIdx.x;
    int tid = threadIdx.x;
    int wid = tid >> 5, lid = tid & 31;

    float4 xv = ((const float4*)(x + (size_t)t * HH))[tid];
    float ss = xv.x*xv.x + xv.y*xv.y + xv.z*xv.z + xv.w*xv.w;
    #pragma unroll
    for (int o = 16; o; o >>= 1) ss += __shfl_xor_sync(0xffffffffu, ss, o);

    __shared__ float sred[8];
    if (lid == 0) sred[wid] = ss;
    __syncthreads();
    float tot = 0.f;
    #pragma unroll
    for (int w = 0; w < 8; w++) tot += sred[w];
    float rinv = rsqrtf(tot / (float)HH + EPSV);

    float4 sv = ((const float4*)nscale)[tid];
    float4 tn;
    tn.x = xv.x * rinv * sv.x;
    tn.y = xv.y * rinv * sv.y;
    tn.z = xv.z * rinv * sv.z;
    tn.w = xv.w * rinv * sv.w;
    ((float4*)(g_tnorm + (size_t)t * HH))[tid] = tn;

    // gate logits in fp32 (routing decisions must match reference)
    int h0 = tid * 4;
    float acc[EE];
    #pragma unroll
    for (int e = 0; e < EE; e++) {
        const float4 gv = *(const float4*)&gw[e * HH + h0];
        acc[e] = tn.x*gv.x + tn.y*gv.y + tn.z*gv.z + tn.w*gv.w;
    }
    #pragma unroll
    for (int o = 16; o; o >>= 1) {
        #pragma unroll
        for (int e = 0; e < EE; e++)
            acc[e] += __shfl_xor_sync(0xffffffffu, acc[e], o);
    }
    __shared__ float sg[8][EE];
    if (lid == 0) {
        #pragma unroll
        for (int e = 0; e < EE; e++) sg[wid][e] = acc[e];
    }
    __syncthreads();
    __shared__ float logits[EE];
    if (tid < EE) {
        float v = gb[tid];
        #pragma unroll
        for (int w = 0; w < 8; w++) v += sg[w][tid];
        logits[tid] = v;
    }
    __syncthreads();

    if (tid == 0) {
        float l[EE];
        #pragma unroll
        for (int e = 0; e < EE; e++) l[e] = logits[e];
        float vals[KK]; int ids[KK];
        #pragma unroll
        for (int k = 0; k < KK; k++) {
            int bi = 0; float bv = l[0];
            #pragma unroll
            for (int e = 1; e < EE; e++) if (l[e] > bv) { bv = l[e]; bi = e; }
            vals[k] = bv; ids[k] = bi; l[bi] = -INFINITY;
        }
        float mx = vals[0];
        float wv[KK]; float s = 0.f;
        #pragma unroll
        for (int k = 0; k < KK; k++) { wv[k] = expf(vals[k] - mx); s += wv[k]; }
        float inv = 1.f / s;
        #pragma unroll
        for (int k = 0; k < KK; k++) {
            g_topk_e[t*KK + k] = ids[k];
            g_topk_w[t*KK + k] = wv[k] * inv;
            atomicAdd(&g_cnt[ids[k]], 1);
        }
    }
}

// ---------------- kernel 2: prefix sum over 16 counts -----------------------
__global__ void k_prefix() {
    if (threadIdx.x == 0) {
        int s = 0;
        for (int e = 0; e < EE; e++) {
            g_base[e] = s; g_cursor[e] = s; s += g_cnt[e];
        }
    }
}

// ---------------- kernel 3: fill routing tables -----------------------------
__global__ void k_route() {
    int p = blockIdx.x * blockDim.x + threadIdx.x;
    if (p >= PP) return;
    int e = g_topk_e[p];
    int pos = atomicAdd(&g_cursor[e], 1);
    g_slot_tok[pos] = p / KK;
    g_pair_slot[p] = pos;
}

// ---------------- GEMM1: h = tnorm @ W1^T, fused bias+swiglu ----------------
// tile: 128 slots (M) x 128 h-cols (N) x 16 (K); 256 threads, 8x8 per thread
__global__ __launch_bounds__(256) void k_gemm1(
    const float* __restrict__ w1, const float* __restrict__ b1)
{
    int e = blockIdx.z;
    int cnt = g_cnt[e];
    int m0 = blockIdx.y * 128;
    if (m0 >= cnt) return;
    int base = g_base[e];
    int n0 = blockIdx.x * 128;  // within 2I = 2048
    const float* W = w1 + (size_t)e * 2 * II * HH;

    __shared__ int toks[128];
    __shared__ float As[16][132];
    __shared__ float Bs[16][132];
    int tid = threadIdx.x;
    if (tid < 128) {
        int r = m0 + tid;
        toks[tid] = (r < cnt) ? g_slot_tok[base + r] : -1;
    }
    __syncthreads();

    unsigned long long acc[8][4];
    #pragma unroll
    for (int i = 0; i < 8; i++)
        #pragma unroll
        for (int j = 0; j < 4; j++) acc[i][j] = 0ull;

    int tm = (tid >> 4) << 3;
    int tn = (tid & 15) << 3;

    for (int k0 = 0; k0 < HH; k0 += 16) {
        #pragma unroll
        for (int r = 0; r < 2; r++) {
            int idx = tid + r * 256;
            int row = idx >> 2;
            int kq  = (idx & 3) << 2;
            int tok = toks[row];
            float4 av = make_float4(0.f, 0.f, 0.f, 0.f);
            if (tok >= 0) av = *(const float4*)&g_tnorm[(size_t)tok * HH + k0 + kq];
            As[kq+0][row] = av.x; As[kq+1][row] = av.y;
            As[kq+2][row] = av.z; As[kq+3][row] = av.w;
            float4 bv = *(const float4*)&W[(size_t)(n0 + row) * HH + k0 + kq];
            Bs[kq+0][row] = bv.x; Bs[kq+1][row] = bv.y;
            Bs[kq+2][row] = bv.z; Bs[kq+3][row] = bv.w;
        }
        __syncthreads();
        #pragma unroll
        for (int kk = 0; kk < 16; kk++) {
            float4 a0 = *(const float4*)&As[kk][tm];
            float4 a1 = *(const float4*)&As[kk][tm + 4];
            ulonglong2 bq0 = *(const ulonglong2*)&Bs[kk][tn];
            ulonglong2 bq1 = *(const ulonglong2*)&Bs[kk][tn + 4];
            unsigned long long bp0 = bq0.x, bp1 = bq0.y, bp2 = bq1.x, bp3 = bq1.y;
            float av[8] = {a0.x, a0.y, a0.z, a0.w, a1.x, a1.y, a1.z, a1.w};
            #pragma unroll
            for (int i = 0; i < 8; i++) {
                unsigned long long ap = pk2(av[i], av[i]);
                fma2(acc[i][0], ap, bp0);
                fma2(acc[i][1], ap, bp1);
                fma2(acc[i][2], ap, bp2);
                fma2(acc[i][3], ap, bp3);
            }
        }
        __syncthreads();
    }

    // epilogue: bias + swiglu on (even,odd) pairs -> 4 act cols per thread col-group
    int icol = (n0 + tn) >> 1;
    const float* bb = b1 + e * 2 * II + n0 + tn;
    float be[4], bo[4];
    #pragma unroll
    for (int j = 0; j < 4; j++) { be[j] = bb[2*j]; bo[j] = bb[2*j + 1]; }
    #pragma unroll
    for (int i = 0; i < 8; i++) {
        int m = m0 + tm + i;
        if (m >= cnt) continue;
        int slot = base + m;
        float ov[4];
        #pragma unroll
        for (int j = 0; j < 4; j++) {
            float2 hv = unpk(acc[i][j]);
            float he = hv.x + be[j];
            float ho = hv.y + bo[j];
            float glu = fminf(he, LIMIT);
            float lin = fminf(fmaxf(ho, -LIMIT), LIMIT);
            float sgm = 1.f / (1.f + expf(-ALPHA * glu));
            ov[j] = glu * sgm * (lin + 1.f);
        }
        *(float4*)&g_act[(size_t)slot * II + icol] = make_float4(ov[0], ov[1], ov[2], ov[3]);
    }
}

// ---------------- GEMM2: ypair = act @ W2^T ---------------------------------
__global__ __launch_bounds__(256) void k_gemm2(const float* __restrict__ w2)
{
    int e = blockIdx.z;
    int cnt = g_cnt[e];
    int m0 = blockIdx.y * 128;
    if (m0 >= cnt) return;
    int base = g_base[e];
    int n0 = blockIdx.x * 128;  // within H
    const float* W = w2 + (size_t)e * HH * II;

    __shared__ float As[16][132];
    __shared__ float Bs[16][132];
    int tid = threadIdx.x;

    unsigned long long acc[8][4];
    #pragma unroll
    for (int i = 0; i < 8; i++)
        #pragma unroll
        for (int j = 0; j < 4; j++) acc[i][j] = 0ull;

    int tm = (tid >> 4) << 3;
    int tn = (tid & 15) << 3;

    for (int k0 = 0; k0 < II; k0 += 16) {
        #pragma unroll
        for (int r = 0; r < 2; r++) {
            int idx = tid + r * 256;
            int row = idx >> 2;
            int kq  = (idx & 3) << 2;
            float4 av = make_float4(0.f, 0.f, 0.f, 0.f);
            if (m0 + row < cnt)
                av = *(const float4*)&g_act[(size_t)(base + m0 + row) * II + k0 + kq];
            As[kq+0][row] = av.x; As[kq+1][row] = av.y;
            As[kq+2][row] = av.z; As[kq+3][row] = av.w;
            float4 bv = *(const float4*)&W[(size_t)(n0 + row) * II + k0 + kq];
            Bs[kq+0][row] = bv.x; Bs[kq+1][row] = bv.y;
            Bs[kq+2][row] = bv.z; Bs[kq+3][row] = bv.w;
        }
        __syncthreads();
        #pragma unroll
        for (int kk = 0; kk < 16; kk++) {
            float4 a0 = *(const float4*)&As[kk][tm];
            float4 a1 = *(const float4*)&As[kk][tm + 4];
            ulonglong2 bq0 = *(const ulonglong2*)&Bs[kk][tn];
            ulonglong2 bq1 = *(const ulonglong2*)&Bs[kk][tn + 4];
            unsigned long long bp0 = bq0.x, bp1 = bq0.y, bp2 = bq1.x, bp3 = bq1.y;
            float av[8] = {a0.x, a0.y, a0.z, a0.w, a1.x, a1.y, a1.z, a1.w};
            #pragma unroll
            for (int i = 0; i < 8; i++) {
                unsigned long long ap = pk2(av[i], av[i]);
                fma2(acc[i][0], ap, bp0);
                fma2(acc[i][1], ap, bp1);
                fma2(acc[i][2], ap, bp2);
                fma2(acc[i][3], ap, bp3);
            }
        }
        __syncthreads();
    }

    #pragma unroll
    for (int i = 0; i < 8; i++) {
        int m = m0 + tm + i;
        if (m >= cnt) continue;
        int slot = base + m;
        float2 y0 = unpk(acc[i][0]);
        float2 y1 = unpk(acc[i][1]);
        float2 y2 = unpk(acc[i][2]);
        float2 y3 = unpk(acc[i][3]);
        float* dst = &g_ypair[(size_t)slot * HH + n0 + tn];
        *(float4*)(dst)     = make_float4(y0.x, y0.y, y1.x, y1.y);
        *(float4*)(dst + 4) = make_float4(y2.x, y2.y, y3.x, y3.y);
    }
}

// ---------------- final: out = x + sum_k w_k * (ypair + b2[e]) --------------
__global__ __launch_bounds__(256) void k_final(
    const float* __restrict__ x, const float* __restrict__ b2, float* __restrict__ out)
{
    int t = blockIdx.x;
    int tid = threadIdx.x;
    int h0 = tid * 4;
    float4 r = ((const float4*)(x + (size_t)t * HH))[tid];
    #pragma unroll
    for (int k = 0; k < KK; k++) {
        int e   = g_topk_e[t*KK + k];
        float w = g_topk_w[t*KK + k];
        int s   = g_pair_slot[t*KK + k];
        float4 y  = *(const float4*)&g_ypair[(size_t)s * HH + h0];
        float4 bv = *(const float4*)&b2[e * HH + h0];
        r.x += w * (y.x + bv.x);
        r.y += w * (y.y + bv.y);
        r.z += w * (y.z + bv.z);
        r.w += w * (y.w + bv.w);
    }
    ((float4*)(out + (size_t)t * HH))[tid] = r;
}

// ---------------- launcher --------------------------------------------------
extern "C" void kernel_launch(void* const* d_in, const int* in_sizes, int n_in,
                              void* d_out, int out_size)
{
    (void)in_sizes; (void)n_in; (void)out_size;
    const float* x      = (const float*)d_in[0];
    const float* nscale = (const float*)d_in[1];
    const float* gw     = (const float*)d_in[2];
    const float* gb     = (const float*)d_in[3];
    const float* w1     = (const float*)d_in[4];
    const float* b1     = (const float*)d_in[5];
    const float* w2     = (const float*)d_in[6];
    const float* b2     = (const float*)d_in[7];
    float* out = (float*)d_out;

    k_zero<<<1, 32>>>();
    k_norm_gate<<<TT, 256>>>(x, nscale, gw, gb);
    k_prefix<<<1, 32>>>();
    k_route<<<(PP + 255) / 256, 256>>>();
    dim3 g1(16, 16, EE);   // 2I/128, T/128, E
    k_gemm1<<<g1, 256>>>(w1, b1);
    dim3 g2(8, 16, EE);    // H/128, T/128, E
    k_gemm2<<<g2, 256>>>(w2);
    k_final<<<TT, 256>>>(x, b2, out);
}

// round 2
// speedup vs baseline: 3.0614x; 3.0614x over previous
#include <cuda_runtime.h>
#include <math.h>

#define TT 2048
#define HH 1024
#define II 1024
#define EE 16
#define KK 4
#define PP (TT*KK)
#define ALPHA 1.702f
#define LIMIT 7.0f
#define EPSV 1e-5f

// ---------------- scratch (device globals; no allocations allowed) ----------
__device__ float g_tnorm[TT*HH];          // tf32-rounded normalized tokens
__device__ int   g_cnt[EE];
__device__ int   g_base[EE];
__device__ int   g_cursor[EE];
__device__ int   g_slot_tok[PP];          // slot -> token
__device__ int   g_pair_slot[PP];         // (t,k) -> slot
__device__ int   g_topk_e[PP];
__device__ float g_topk_w[PP];
__device__ float g_act[(size_t)PP*II];    // tf32-rounded swiglu activations
__device__ float g_ypair[(size_t)PP*HH];  // per-pair FFN output (fp32)

// ---------------- tf32 helpers ---------------------------------------------
__device__ __forceinline__ float tf32r(float x) {
    unsigned u;
    asm("cvt.rna.tf32.f32 %0, %1;" : "=r"(u) : "f"(x));
    return __uint_as_float(u);
}
__device__ __forceinline__ void mma_tf32(float* d, const unsigned* a, const unsigned* b) {
    asm volatile(
        "mma.sync.aligned.m16n8k8.row.col.f32.tf32.tf32.f32 "
        "{%0,%1,%2,%3},{%4,%5,%6,%7},{%8,%9},{%0,%1,%2,%3};"
        : "+f"(d[0]), "+f"(d[1]), "+f"(d[2]), "+f"(d[3])
        : "r"(a[0]), "r"(a[1]), "r"(a[2]), "r"(a[3]), "r"(b[0]), "r"(b[1]));
}

// ---------------- kernel 0: zero expert counts ------------------------------
__global__ void k_zero() {
    if (threadIdx.x < EE) g_cnt[threadIdx.x] = 0;
}

// ---------------- kernel 1: rmsnorm + gate + top-4 + softmax ----------------
__global__ __launch_bounds__(256) void k_norm_gate(
    const float* __restrict__ x, const float* __restrict__ nscale,
    const float* __restrict__ gw, const float* __restrict__ gb)
{
    int t = blockIdx.x;
    int tid = threadIdx.x;
    int wid = tid >> 5, lid = tid & 31;

    float4 xv = ((const float4*)(x + (size_t)t * HH))[tid];
    float ss = xv.x*xv.x + xv.y*xv.y + xv.z*xv.z + xv.w*xv.w;
    #pragma unroll
    for (int o = 16; o; o >>= 1) ss += __shfl_xor_sync(0xffffffffu, ss, o);

    __shared__ float sred[8];
    if (lid == 0) sred[wid] = ss;
    __syncthreads();
    float tot = 0.f;
    #pragma unroll
    for (int w = 0; w < 8; w++) tot += sred[w];
    float rinv = rsqrtf(tot / (float)HH + EPSV);

    float4 sv = ((const float4*)nscale)[tid];
    float4 tn;
    tn.x = xv.x * rinv * sv.x;
    tn.y = xv.y * rinv * sv.y;
    tn.z = xv.z * rinv * sv.z;
    tn.w = xv.w * rinv * sv.w;
    // store tf32-rounded copy for the GEMM (gate below uses the exact values)
    float4 tq;
    tq.x = tf32r(tn.x); tq.y = tf32r(tn.y); tq.z = tf32r(tn.z); tq.w = tf32r(tn.w);
    ((float4*)(g_tnorm + (size_t)t * HH))[tid] = tq;

    // gate logits in exact fp32 (routing decisions must match reference)
    int h0 = tid * 4;
    float acc[EE];
    #pragma unroll
    for (int e = 0; e < EE; e++) {
        const float4 gv = *(const float4*)&gw[e * HH + h0];
        acc[e] = tn.x*gv.x + tn.y*gv.y + tn.z*gv.z + tn.w*gv.w;
    }
    #pragma unroll
    for (int o = 16; o; o >>= 1) {
        #pragma unroll
        for (int e = 0; e < EE; e++)
            acc[e] += __shfl_xor_sync(0xffffffffu, acc[e], o);
    }
    __shared__ float sg[8][EE];
    if (lid == 0) {
        #pragma unroll
        for (int e = 0; e < EE; e++) sg[wid][e] = acc[e];
    }
    __syncthreads();
    __shared__ float logits[EE];
    if (tid < EE) {
        float v = gb[tid];
        #pragma unroll
        for (int w = 0; w < 8; w++) v += sg[w][tid];
        logits[tid] = v;
    }
    __syncthreads();

    if (tid == 0) {
        float l[EE];
        #pragma unroll
        for (int e = 0; e < EE; e++) l[e] = logits[e];
        float vals[KK]; int ids[KK];
        #pragma unroll
        for (int k = 0; k < KK; k++) {
            int bi = 0; float bv = l[0];
            #pragma unroll
            for (int e = 1; e < EE; e++) if (l[e] > bv) { bv = l[e]; bi = e; }
            vals[k] = bv; ids[k] = bi; l[bi] = -INFINITY;
        }
        float mx = vals[0];
        float wv[KK]; float s = 0.f;
        #pragma unroll
        for (int k = 0; k < KK; k++) { wv[k] = expf(vals[k] - mx); s += wv[k]; }
        float inv = 1.f / s;
        #pragma unroll
        for (int k = 0; k < KK; k++) {
            g_topk_e[t*KK + k] = ids[k];
            g_topk_w[t*KK + k] = wv[k] * inv;
            atomicAdd(&g_cnt[ids[k]], 1);
        }
    }
}

// ---------------- kernel 2: prefix sum over 16 counts -----------------------
__global__ void k_prefix() {
    if (threadIdx.x == 0) {
        int s = 0;
        for (int e = 0; e < EE; e++) {
            g_base[e] = s; g_cursor[e] = s; s += g_cnt[e];
        }
    }
}

// ---------------- kernel 3: fill routing tables -----------------------------
__global__ void k_route() {
    int p = blockIdx.x * blockDim.x + threadIdx.x;
    if (p >= PP) return;
    int e = g_topk_e[p];
    int pos = atomicAdd(&g_cursor[e], 1);
    g_slot_tok[pos] = p / KK;
    g_pair_slot[p] = pos;
}

// ============================================================================
// tf32 tensor-core GEMMs: tile 128(M) x 128(N) x 32(K), 8 warps (4m x 2n),
// warp tile 32x64 = 2x8 m16n8k8 fragments. Single smem stage + register
// double-buffer for global loads. B (weights) rounded to tf32 in the fill.
// ============================================================================

// ---------------- GEMM1: h = tnorm @ W1^T, fused bias+swiglu ----------------
__global__ __launch_bounds__(256) void k_gemm1(
    const float* __restrict__ w1, const float* __restrict__ b1)
{
    int e = blockIdx.z;
    int cnt = g_cnt[e];
    int m0 = blockIdx.y * 128;
    if (m0 >= cnt) return;
    int base = g_base[e];
    int n0 = blockIdx.x * 128;  // within 2I = 2048
    const float* W = w1 + (size_t)e * 2 * II * HH;

    __shared__ int   toks[128];
    __shared__ float As[128][36];
    __shared__ float Bs[128][36];

    int tid = threadIdx.x;
    int wid = tid >> 5, lane = tid & 31;
    int wm = wid & 3, wn = wid >> 2;
    int lr = lane >> 2, lc = lane & 3;

    if (tid < 128) {
        int r = m0 + tid;
        toks[tid] = (r < cnt) ? g_slot_tok[base + r] : -1;
    }
    __syncthreads();

    int row0 = tid >> 3;        // 0..31
    int q4   = (tid & 7) << 2;  // 0,4,...,28

    float acc[2][8][4];
    #pragma unroll
    for (int mi = 0; mi < 2; mi++)
        #pragma unroll
        for (int ni = 0; ni < 8; ni++)
            #pragma unroll
            for (int j = 0; j < 4; j++) acc[mi][ni][j] = 0.f;

    float4 ra[4], rb[4];
    // prologue: fetch k-tile 0
    #pragma unroll
    for (int i = 0; i < 4; i++) {
        int row = row0 + i * 32;
        int tok = toks[row];
        ra[i] = (tok >= 0) ? *(const float4*)&g_tnorm[(size_t)tok * HH + q4]
                           : make_float4(0.f, 0.f, 0.f, 0.f);
        rb[i] = *(const float4*)&W[(size_t)(n0 + row) * HH + q4];
    }
    #pragma unroll
    for (int i = 0; i < 4; i++) {
        int row = row0 + i * 32;
        *(float4*)&As[row][q4] = ra[i];
        *(float4*)&Bs[row][q4] = make_float4(tf32r(rb[i].x), tf32r(rb[i].y),
                                             tf32r(rb[i].z), tf32r(rb[i].w));
    }
    __syncthreads();

    for (int kt = 0; kt < HH / 32; kt++) {
        int knext = (kt + 1) * 32;
        bool has = knext < HH;
        if (has) {
            #pragma unroll
            for (int i = 0; i < 4; i++) {
                int row = row0 + i * 32;
                int tok = toks[row];
                ra[i] = (tok >= 0) ? *(const float4*)&g_tnorm[(size_t)tok * HH + knext + q4]
                                   : make_float4(0.f, 0.f, 0.f, 0.f);
                rb[i] = *(const float4*)&W[(size_t)(n0 + row) * HH + knext + q4];
            }
        }
        #pragma unroll
        for (int kk = 0; kk < 32; kk += 8) {
            unsigned bf[8][2];
            #pragma unroll
            for (int ni = 0; ni < 8; ni++) {
                int nb = wn * 64 + ni * 8 + lr;
                bf[ni][0] = __float_as_uint(Bs[nb][kk + lc]);
                bf[ni][1] = __float_as_uint(Bs[nb][kk + lc + 4]);
            }
            #pragma unroll
            for (int mi = 0; mi < 2; mi++) {
                int rbm = wm * 32 + mi * 16 + lr;
                unsigned af[4];
                af[0] = __float_as_uint(As[rbm][kk + lc]);
                af[1] = __float_as_uint(As[rbm + 8][kk + lc]);
                af[2] = __float_as_uint(As[rbm][kk + lc + 4]);
                af[3] = __float_as_uint(As[rbm + 8][kk + lc + 4]);
                #pragma unroll
                for (int ni = 0; ni < 8; ni++) mma_tf32(acc[mi][ni], af, bf[ni]);
            }
        }
        __syncthreads();
        if (has) {
            #pragma unroll
            for (int i = 0; i < 4; i++) {
                int row = row0 + i * 32;
                *(float4*)&As[row][q4] = ra[i];
                *(float4*)&Bs[row][q4] = make_float4(tf32r(rb[i].x), tf32r(rb[i].y),
                                                     tf32r(rb[i].z), tf32r(rb[i].w));
            }
            __syncthreads();
        }
    }

    // epilogue: bias + swiglu; acc cols (c0,c1) and (c2,c3) are (even,odd) pairs
    #pragma unroll
    for (int ni = 0; ni < 8; ni++) {
        int ng = n0 + wn * 64 + ni * 8 + 2 * lc;  // even column in [0,2I)
        float be = b1[e * 2 * II + ng];
        float bo = b1[e * 2 * II + ng + 1];
        int icol = ng >> 1;
        #pragma unroll
        for (int mi = 0; mi < 2; mi++) {
            int r = m0 + wm * 32 + mi * 16 + lr;
            #pragma unroll
            for (int half = 0; half < 2; half++) {
                int rr = r + half * 8;
                if (rr >= cnt) continue;
                float he = acc[mi][ni][2 * half]     + be;
                float ho = acc[mi][ni][2 * half + 1] + bo;
                float glu = fminf(he, LIMIT);
                float lin = fminf(fmaxf(ho, -LIMIT), LIMIT);
                float sgm = 1.f / (1.f + expf(-ALPHA * glu));
                g_act[(size_t)(base + rr) * II + icol] = tf32r(glu * sgm * (lin + 1.f));
            }
        }
    }
}

// ---------------- GEMM2: ypair = act @ W2^T ---------------------------------
__global__ __launch_bounds__(256) void k_gemm2(const float* __restrict__ w2)
{
    int e = blockIdx.z;
    int cnt = g_cnt[e];
    int m0 = blockIdx.y * 128;
    if (m0 >= cnt) return;
    int base = g_base[e];
    int n0 = blockIdx.x * 128;  // within H
    const float* W = w2 + (size_t)e * HH * II;

    __shared__ float As[128][36];
    __shared__ float Bs[128][36];

    int tid = threadIdx.x;
    int wid = tid >> 5, lane = tid & 31;
    int wm = wid & 3, wn = wid >> 2;
    int lr = lane >> 2, lc = lane & 3;

    int row0 = tid >> 3;
    int q4   = (tid & 7) << 2;

    float acc[2][8][4];
    #pragma unroll
    for (int mi = 0; mi < 2; mi++)
        #pragma unroll
        for (int ni = 0; ni < 8; ni++)
            #pragma unroll
            for (int j = 0; j < 4; j++) acc[mi][ni][j] = 0.f;

    float4 ra[4], rb[4];
    #pragma unroll
    for (int i = 0; i < 4; i++) {
        int row = row0 + i * 32;
        ra[i] = (m0 + row < cnt) ? *(const float4*)&g_act[(size_t)(base + m0 + row) * II + q4]
                                 : make_float4(0.f, 0.f, 0.f, 0.f);
        rb[i] = *(const float4*)&W[(size_t)(n0 + row) * II + q4];
    }
    #pragma unroll
    for (int i = 0; i < 4; i++) {
        int row = row0 + i * 32;
        *(float4*)&As[row][q4] = ra[i];
        *(float4*)&Bs[row][q4] = make_float4(tf32r(rb[i].x), tf32r(rb[i].y),
                                             tf32r(rb[i].z), tf32r(rb[i].w));
    }
    __syncthreads();

    for (int kt = 0; kt < II / 32; kt++) {
        int knext = (kt + 1) * 32;
        bool has = knext < II;
        if (has) {
            #pragma unroll
            for (int i = 0; i < 4; i++) {
                int row = row0 + i * 32;
                ra[i] = (m0 + row < cnt)
                          ? *(const float4*)&g_act[(size_t)(base + m0 + row) * II + knext + q4]
                          : make_float4(0.f, 0.f, 0.f, 0.f);
                rb[i] = *(const float4*)&W[(size_t)(n0 + row) * II + knext + q4];
            }
        }
        #pragma unroll
        for (int kk = 0; kk < 32; kk += 8) {
            unsigned bf[8][2];
            #pragma unroll
            for (int ni = 0; ni < 8; ni++) {
                int nb = wn * 64 + ni * 8 + lr;
                bf[ni][0] = __float_as_uint(Bs[nb][kk + lc]);
                bf[ni][1] = __float_as_uint(Bs[nb][kk + lc + 4]);
            }
            #pragma unroll
            for (int mi = 0; mi < 2; mi++) {
                int rbm = wm * 32 + mi * 16 + lr;
                unsigned af[4];
                af[0] = __float_as_uint(As[rbm][kk + lc]);
                af[1] = __float_as_uint(As[rbm + 8][kk + lc]);
                af[2] = __float_as_uint(As[rbm][kk + lc + 4]);
                af[3] = __float_as_uint(As[rbm + 8][kk + lc + 4]);
                #pragma unroll
                for (int ni = 0; ni < 8; ni++) mma_tf32(acc[mi][ni], af, bf[ni]);
            }
        }
        __syncthreads();
        if (has) {
            #pragma unroll
            for (int i = 0; i < 4; i++) {
                int row = row0 + i * 32;
                *(float4*)&As[row][q4] = ra[i];
                *(float4*)&Bs[row][q4] = make_float4(tf32r(rb[i].x), tf32r(rb[i].y),
                                                     tf32r(rb[i].z), tf32r(rb[i].w));
            }
            __syncthreads();
        }
    }

    #pragma unroll
    for (int ni = 0; ni < 8; ni++) {
        int ng = n0 + wn * 64 + ni * 8 + 2 * lc;
        #pragma unroll
        for (int mi = 0; mi < 2; mi++) {
            int r = m0 + wm * 32 + mi * 16 + lr;
            #pragma unroll
            for (int half = 0; half < 2; half++) {
                int rr = r + half * 8;
                if (rr >= cnt) continue;
                float2 v = make_float2(acc[mi][ni][2 * half], acc[mi][ni][2 * half + 1]);
                *(float2*)&g_ypair[(size_t)(base + rr) * HH + ng] = v;
            }
        }
    }
}

// ---------------- final: out = x + sum_k w_k * (ypair + b2[e]) --------------
__global__ __launch_bounds__(256) void k_final(
    const float* __restrict__ x, const float* __restrict__ b2, float* __restrict__ out)
{
    int t = blockIdx.x;
    int tid = threadIdx.x;
    int h0 = tid * 4;
    float4 r = ((const float4*)(x + (size_t)t * HH))[tid];
    #pragma unroll
    for (int k = 0; k < KK; k++) {
        int e   = g_topk_e[t*KK + k];
        float w = g_topk_w[t*KK + k];
        int s   = g_pair_slot[t*KK + k];
        float4 y  = *(const float4*)&g_ypair[(size_t)s * HH + h0];
        float4 bv = *(const float4*)&b2[e * HH + h0];
        r.x += w * (y.x + bv.x);
        r.y += w * (y.y + bv.y);
        r.z += w * (y.z + bv.z);
        r.w += w * (y.w + bv.w);
    }
    ((float4*)(out + (size_t)t * HH))[tid] = r;
}

// ---------------- launcher --------------------------------------------------
extern "C" void kernel_launch(void* const* d_in, const int* in_sizes, int n_in,
                              void* d_out, int out_size)
{
    (void)in_sizes; (void)n_in; (void)out_size;
    const float* x      = (const float*)d_in[0];
    const float* nscale = (const float*)d_in[1];
    const float* gw     = (const float*)d_in[2];
    const float* gb     = (const float*)d_in[3];
    const float* w1     = (const float*)d_in[4];
    const float* b1     = (const float*)d_in[5];
    const float* w2     = (const float*)d_in[6];
    const float* b2     = (const float*)d_in[7];
    float* out = (float*)d_out;

    k_zero<<<1, 32>>>();
    k_norm_gate<<<TT, 256>>>(x, nscale, gw, gb);
    k_prefix<<<1, 32>>>();
    k_route<<<(PP + 255) / 256, 256>>>();
    dim3 g1(16, 16, EE);   // 2I/128, T/128, E
    k_gemm1<<<g1, 256>>>(w1, b1);
    dim3 g2(8, 16, EE);    // H/128, T/128, E
    k_gemm2<<<g2, 256>>>(w2);
    k_final<<<TT, 256>>>(x, b2, out);
}

// round 3
// speedup vs baseline: 3.6833x; 1.2031x over previous
#include <cuda_runtime.h>
#include <cuda_bf16.h>
#include <math.h>

#define TT 2048
#define HH 1024
#define II 1024
#define EE 16
#define KK 4
#define PP (TT*KK)
#define ALPHA 1.702f
#define LIMIT 7.0f
#define EPSV 1e-5f

// GEMM tiling
#define KT 64                 // k per stage (bf16 elements) -> 128B rows
#define ROWB 128              // bytes per smem row
#define A_STAGES 3
#define A_STAGE_BYTES (128*ROWB)      // 16 KB
#define B_STAGE_BYTES (256*ROWB)      // 32 KB
#define SMEM_A_OFF 0
#define SMEM_B_OFF (A_STAGES*A_STAGE_BYTES)            // 49152
#define SMEM_TOKS_OFF (SMEM_B_OFF + 2*B_STAGE_BYTES)   // 114688
#define SMEM_TOTAL (SMEM_TOKS_OFF + 512)               // 115200

// ---------------- scratch ----------------------------------------------------
__device__ __nv_bfloat16 g_tnorm[(size_t)TT*HH];
__device__ int   g_cnt[EE];
__device__ int   g_base[EE];
__device__ int   g_cursor[EE];
__device__ int   g_slot_tok[PP];
__device__ int   g_pair_slot[PP];
__device__ int   g_topk_e[PP];
__device__ float g_topk_w[PP];
__device__ __nv_bfloat16 g_act[(size_t)PP*II];
__device__ float g_ypair[(size_t)PP*HH];

// ---------------- asm helpers ------------------------------------------------
__device__ __forceinline__ unsigned su32(const void* p) {
    return (unsigned)__cvta_generic_to_shared(p);
}
__device__ __forceinline__ void cp16(unsigned dst, const void* src, int sz) {
    asm volatile("cp.async.cg.shared.global [%0], [%1], 16, %2;\n"
                 :: "r"(dst), "l"(src), "r"(sz));
}
__device__ __forceinline__ void cp_commit() { asm volatile("cp.async.commit_group;"); }
__device__ __forceinline__ void cp_wait1()  { asm volatile("cp.async.wait_group 1;"); }
__device__ __forceinline__ void ldsm4(unsigned* r, unsigned addr) {
    asm volatile("ldmatrix.sync.aligned.m8n8.x4.shared.b16 {%0,%1,%2,%3}, [%4];"
                 : "=r"(r[0]), "=r"(r[1]), "=r"(r[2]), "=r"(r[3]) : "r"(addr));
}
__device__ __forceinline__ void mma_bf16(float* d, const unsigned* a, const unsigned* b) {
    asm volatile(
        "mma.sync.aligned.m16n8k16.row.col.f32.bf16.bf16.f32 "
        "{%0,%1,%2,%3},{%4,%5,%6,%7},{%8,%9},{%0,%1,%2,%3};"
        : "+f"(d[0]), "+f"(d[1]), "+f"(d[2]), "+f"(d[3])
        : "r"(a[0]), "r"(a[1]), "r"(a[2]), "r"(a[3]), "r"(b[0]), "r"(b[1]));
}
__device__ __forceinline__ unsigned pk_bf16x2(float lo, float hi) {
    __nv_bfloat162 v = __floats2bfloat162_rn(lo, hi);  // .x = lo half in memory
    return *(unsigned*)&v;
}

// ---------------- kernel 0: zero expert counts -------------------------------
__global__ void k_zero() {
    if (threadIdx.x < EE) g_cnt[threadIdx.x] = 0;
}

// ---------------- kernel 1: rmsnorm + gate + top-4 + softmax -----------------
__global__ __launch_bounds__(256) void k_norm_gate(
    const float* __restrict__ x, const float* __restrict__ nscale,
    const float* __restrict__ gw, const float* __restrict__ gb)
{
    int t = blockIdx.x;
    int tid = threadIdx.x;
    int wid = tid >> 5, lid = tid & 31;

    float4 xv = ((const float4*)(x + (size_t)t * HH))[tid];
    float ss = xv.x*xv.x + xv.y*xv.y + xv.z*xv.z + xv.w*xv.w;
    #pragma unroll
    for (int o = 16; o; o >>= 1) ss += __shfl_xor_sync(0xffffffffu, ss, o);

    __shared__ float sred[8];
    if (lid == 0) sred[wid] = ss;
    __syncthreads();
    float tot = 0.f;
    #pragma unroll
    for (int w = 0; w < 8; w++) tot += sred[w];
    float rinv = rsqrtf(tot / (float)HH + EPSV);

    float4 sv = ((const float4*)nscale)[tid];
    float4 tn;
    tn.x = xv.x * rinv * sv.x;
    tn.y = xv.y * rinv * sv.y;
    tn.z = xv.z * rinv * sv.z;
    tn.w = xv.w * rinv * sv.w;
    // bf16 copy for the GEMMs (gate uses exact fp32 below)
    unsigned p0 = pk_bf16x2(tn.x, tn.y);
    unsigned p1 = pk_bf16x2(tn.z, tn.w);
    ((uint2*)(g_tnorm + (size_t)t * HH))[tid] = make_uint2(p0, p1);

    int h0 = tid * 4;
    float acc[EE];
    #pragma unroll
    for (int e = 0; e < EE; e++) {
        const float4 gv = *(const float4*)&gw[e * HH + h0];
        acc[e] = tn.x*gv.x + tn.y*gv.y + tn.z*gv.z + tn.w*gv.w;
    }
    #pragma unroll
    for (int o = 16; o; o >>= 1) {
        #pragma unroll
        for (int e = 0; e < EE; e++)
            acc[e] += __shfl_xor_sync(0xffffffffu, acc[e], o);
    }
    __shared__ float sg[8][EE];
    if (lid == 0) {
        #pragma unroll
        for (int e = 0; e < EE; e++) sg[wid][e] = acc[e];
    }
    __syncthreads();
    __shared__ float logits[EE];
    if (tid < EE) {
        float v = gb[tid];
        #pragma unroll
        for (int w = 0; w < 8; w++) v += sg[w][tid];
        logits[tid] = v;
    }
    __syncthreads();

    if (tid == 0) {
        float l[EE];
        #pragma unroll
        for (int e = 0; e < EE; e++) l[e] = logits[e];
        float vals[KK]; int ids[KK];
        #pragma unroll
        for (int k = 0; k < KK; k++) {
            int bi = 0; float bv = l[0];
            #pragma unroll
            for (int e = 1; e < EE; e++) if (l[e] > bv) { bv = l[e]; bi = e; }
            vals[k] = bv; ids[k] = bi; l[bi] = -INFINITY;
        }
        float mx = vals[0];
        float wv[KK]; float s = 0.f;
        #pragma unroll
        for (int k = 0; k < KK; k++) { wv[k] = expf(vals[k] - mx); s += wv[k]; }
        float inv = 1.f / s;
        #pragma unroll
        for (int k = 0; k < KK; k++) {
            g_topk_e[t*KK + k] = ids[k];
            g_topk_w[t*KK + k] = wv[k] * inv;
            atomicAdd(&g_cnt[ids[k]], 1);
        }
    }
}

// ---------------- kernel 2/3: prefix + routing -------------------------------
__global__ void k_prefix() {
    if (threadIdx.x == 0) {
        int s = 0;
        for (int e = 0; e < EE; e++) { g_base[e] = s; g_cursor[e] = s; s += g_cnt[e]; }
    }
}
__global__ void k_route() {
    int p = blockIdx.x * blockDim.x + threadIdx.x;
    if (p >= PP) return;
    int e = g_topk_e[p];
    int pos = atomicAdd(&g_cursor[e], 1);
    g_slot_tok[pos] = p / KK;
    g_pair_slot[p] = pos;
}

// ============================================================================
// bf16 GEMMs: CTA tile 128M x 256N x 64K, 8 warps (2m x 4n), warp tile 64x64.
// A via cp.async (bf16 in gmem), B via LDG f32 -> cvt -> STS (double buffer).
// Fragments via ldmatrix.x4 from 128B swizzled rows (chunk ^= row&7).
// ============================================================================

// shared-mem fill of B (weights): rows = n (256), k-half h covers 32 floats
__device__ __forceinline__ void ldgB(float4* bb, const float* __restrict__ Wrow, int h) {
    const float4* p = (const float4*)(Wrow + h * 32);
    #pragma unroll
    for (int j = 0; j < 8; j++) bb[j] = p[j];
}
__device__ __forceinline__ void stsB(char* smB, const float4* bb, int r, int h) {
    #pragma unroll
    for (int c = 0; c < 4; c++) {
        unsigned q0 = pk_bf16x2(bb[2*c].x, bb[2*c].y);
        unsigned q1 = pk_bf16x2(bb[2*c].z, bb[2*c].w);
        unsigned q2 = pk_bf16x2(bb[2*c+1].x, bb[2*c+1].y);
        unsigned q3 = pk_bf16x2(bb[2*c+1].z, bb[2*c+1].w);
        int ch = 4*h + c;
        *(uint4*)(smB + r*ROWB + ((ch ^ (r & 7)) * 16)) = make_uint4(q0, q1, q2, q3);
    }
}

// one k16 step of MMAs for the whole warp tile
__device__ __forceinline__ void do_ks(
    unsigned aBase, unsigned bBase, int ks, int wm, int wn, int lane,
    float acc[4][8][4])
{
    int q = lane >> 3, rr = lane & 7;
    unsigned a[4][4];
    #pragma unroll
    for (int mi = 0; mi < 4; mi++) {
        int row = wm*64 + mi*16 + (q & 1)*8 + rr;
        int ch  = 2*ks + (q >> 1);
        ldsm4(a[mi], aBase + row*ROWB + ((ch ^ (row & 7)) * 16));
    }
    unsigned b[8][2];
    #pragma unroll
    for (int p = 0; p < 4; p++) {
        int row = wn*64 + p*16 + (q >> 1)*8 + rr;
        int ch  = 2*ks + (q & 1);
        unsigned r4[4];
        ldsm4(r4, bBase + row*ROWB + ((ch ^ (row & 7)) * 16));
        b[2*p][0] = r4[0]; b[2*p][1] = r4[1];
        b[2*p+1][0] = r4[2]; b[2*p+1][1] = r4[3];
    }
    #pragma unroll
    for (int mi = 0; mi < 4; mi++)
        #pragma unroll
        for (int ni = 0; ni < 8; ni++)
            mma_bf16(acc[mi][ni], a[mi], b[ni]);
}

// ---------------- GEMM1: h = tnorm @ W1^T, fused bias+swiglu -----------------
__global__ __launch_bounds__(256, 1) void k_gemm1(
    const float* __restrict__ w1, const float* __restrict__ b1)
{
    extern __shared__ char sm[];
    char* smA = sm + SMEM_A_OFF;
    char* smB = sm + SMEM_B_OFF;
    int*  toks = (int*)(sm + SMEM_TOKS_OFF);

    int e = blockIdx.z;
    int cnt = g_cnt[e];
    int m0 = blockIdx.y * 128;
    if (m0 >= cnt) return;
    int base = g_base[e];
    int n0 = blockIdx.x * 256;  // within 2I
    const float* W = w1 + (size_t)e * 2 * II * HH;

    int tid = threadIdx.x;
    int wid = tid >> 5, lane = tid & 31;
    int wm = wid & 1, wn = wid >> 1;
    int lr = lane >> 2, lc = lane & 3;

    if (tid < 128) {
        int r = m0 + tid;
        toks[tid] = (r < cnt) ? g_slot_tok[base + r] : 0x7fffffff;
    }
    __syncthreads();

    // per-thread A fill coords: 4 chunks
    int ar = tid >> 1;
    int acb = (tid & 1) * 4;
    unsigned aBaseAll = su32(smA);
    unsigned bBaseAll = su32(smB);

    const float* Wrow = W + (size_t)(n0 + tid) * HH;   // thread owns B row tid

    // prologue: A stages 0,1
    #pragma unroll 1
    for (int s = 0; s < 2; s++) {
        int tok = toks[ar];
        bool v = (tok != 0x7fffffff);
        const __nv_bfloat16* src = g_tnorm + (size_t)(v ? tok : 0) * HH + s*KT;
        unsigned dst = aBaseAll + s*A_STAGE_BYTES + ar*ROWB;
        #pragma unroll
        for (int c = 0; c < 4; c++) {
            int ch = acb + c;
            cp16(dst + ((ch ^ (ar & 7)) * 16), src + ch*8, v ? 16 : 0);
        }
        cp_commit();
    }
    // B stage 0 (both halves), then preload half0 of kt=1
    float4 bb[8];
    ldgB(bb, Wrow, 0); stsB(smB, bb, tid, 0);
    ldgB(bb, Wrow + 32, 0); stsB(smB, bb, tid, 1);
    ldgB(bb, Wrow + KT, 0);

    float acc[4][8][4];
    #pragma unroll
    for (int mi = 0; mi < 4; mi++)
        #pragma unroll
        for (int ni = 0; ni < 8; ni++)
            #pragma unroll
            for (int j = 0; j < 4; j++) acc[mi][ni][j] = 0.f;

    const int NK = HH / KT;  // 16
    #pragma unroll 1
    for (int kt = 0; kt < NK; kt++) {
        cp_wait1();
        __syncthreads();
        unsigned aB = aBaseAll + (kt % 3) * A_STAGE_BYTES;
        unsigned bB = bBaseAll + (kt & 1) * B_STAGE_BYTES;
        char*    bS = smB + ((kt + 1) & 1) * B_STAGE_BYTES;

        do_ks(aB, bB, 0, wm, wn, lane, acc);
        do_ks(aB, bB, 1, wm, wn, lane, acc);
        if (kt + 1 < NK) {
            stsB(bS, bb, tid, 0);
            ldgB(bb, Wrow + (kt + 1) * KT + 32, 0);
        }
        do_ks(aB, bB, 2, wm, wn, lane, acc);
        do_ks(aB, bB, 3, wm, wn, lane, acc);
        if (kt + 1 < NK) stsB(bS, bb, tid, 1);
        if (kt + 2 < NK) {
            ldgB(bb, Wrow + (kt + 2) * KT, 0);
            int tok = toks[ar];
            bool v = (tok != 0x7fffffff);
            const __nv_bfloat16* src = g_tnorm + (size_t)(v ? tok : 0) * HH + (kt + 2) * KT;
            unsigned dst = aBaseAll + ((kt + 2) % 3) * A_STAGE_BYTES + ar*ROWB;
            #pragma unroll
            for (int c = 0; c < 4; c++) {
                int ch = acb + c;
                cp16(dst + ((ch ^ (ar & 7)) * 16), src + ch*8, v ? 16 : 0);
            }
        }
        cp_commit();
    }

    // epilogue: bias + swiglu -> g_act (bf16)
    #pragma unroll
    for (int ni = 0; ni < 8; ni++) {
        int ng = n0 + wn*64 + ni*8 + 2*lc;        // even col in [0,2I)
        float be = b1[e * 2 * II + ng];
        float bo = b1[e * 2 * II + ng + 1];
        int icol = ng >> 1;
        #pragma unroll
        for (int mi = 0; mi < 4; mi++) {
            int mrow = m0 + wm*64 + mi*16 + lr;
            #pragma unroll
            for (int half = 0; half < 2; half++) {
                int rr = mrow + half * 8;
                if (rr >= cnt) continue;
                float he = acc[mi][ni][2*half]     + be;
                float ho = acc[mi][ni][2*half + 1] + bo;
                float glu = fminf(he, LIMIT);
                float lin = fminf(fmaxf(ho, -LIMIT), LIMIT);
                float sgm = 1.f / (1.f + expf(-ALPHA * glu));
                g_act[(size_t)(base + rr) * II + icol] = __float2bfloat16(glu * sgm * (lin + 1.f));
            }
        }
    }
}

// ---------------- GEMM2: ypair = act @ W2^T ----------------------------------
__global__ __launch_bounds__(256, 1) void k_gemm2(const float* __restrict__ w2)
{
    extern __shared__ char sm[];
    char* smA = sm + SMEM_A_OFF;
    char* smB = sm + SMEM_B_OFF;

    int e = blockIdx.z;
    int cnt = g_cnt[e];
    int m0 = blockIdx.y * 128;
    if (m0 >= cnt) return;
    int base = g_base[e];
    int n0 = blockIdx.x * 256;  // within H
    const float* W = w2 + (size_t)e * HH * II;

    int tid = threadIdx.x;
    int wid = tid >> 5, lane = tid & 31;
    int wm = wid & 1, wn = wid >> 1;
    int lr = lane >> 2, lc = lane & 3;

    int ar = tid >> 1;
    int acb = (tid & 1) * 4;
    unsigned aBaseAll = su32(smA);
    unsigned bBaseAll = su32(smB);

    bool avalid = (m0 + ar < cnt);
    const __nv_bfloat16* Arow = g_act + (size_t)(base + (avalid ? m0 + ar : 0)) * II;
    const float* Wrow = W + (size_t)(n0 + tid) * II;

    #pragma unroll 1
    for (int s = 0; s < 2; s++) {
        unsigned dst = aBaseAll + s*A_STAGE_BYTES + ar*ROWB;
        #pragma unroll
        for (int c = 0; c < 4; c++) {
            int ch = acb + c;
            cp16(dst + ((ch ^ (ar & 7)) * 16), Arow + s*KT + ch*8, avalid ? 16 : 0);
        }
        cp_commit();
    }
    float4 bb[8];
    ldgB(bb, Wrow, 0); stsB(smB, bb, tid, 0);
    ldgB(bb, Wrow + 32, 0); stsB(smB, bb, tid, 1);
    ldgB(bb, Wrow + KT, 0);

    float acc[4][8][4];
    #pragma unroll
    for (int mi = 0; mi < 4; mi++)
        #pragma unroll
        for (int ni = 0; ni < 8; ni++)
            #pragma unroll
            for (int j = 0; j < 4; j++) acc[mi][ni][j] = 0.f;

    const int NK = II / KT;  // 16
    #pragma unroll 1
    for (int kt = 0; kt < NK; kt++) {
        cp_wait1();
        __syncthreads();
        unsigned aB = aBaseAll + (kt % 3) * A_STAGE_BYTES;
        unsigned bB = bBaseAll + (kt & 1) * B_STAGE_BYTES;
        char*    bS = smB + ((kt + 1) & 1) * B_STAGE_BYTES;

        do_ks(aB, bB, 0, wm, wn, lane, acc);
        do_ks(aB, bB, 1, wm, wn, lane, acc);
        if (kt + 1 < NK) {
            stsB(bS, bb, tid, 0);
            ldgB(bb, Wrow + (kt + 1) * KT + 32, 0);
        }
        do_ks(aB, bB, 2, wm, wn, lane, acc);
        do_ks(aB, bB, 3, wm, wn, lane, acc);
        if (kt + 1 < NK) stsB(bS, bb, tid, 1);
        if (kt + 2 < NK) {
            ldgB(bb, Wrow + (kt + 2) * KT, 0);
            unsigned dst = aBaseAll + ((kt + 2) % 3) * A_STAGE_BYTES + ar*ROWB;
            #pragma unroll
            for (int c = 0; c < 4; c++) {
                int ch = acb + c;
                cp16(dst + ((ch ^ (ar & 7)) * 16), Arow + (kt + 2)*KT + ch*8, avalid ? 16 : 0);
            }
        }
        cp_commit();
    }

    #pragma unroll
    for (int ni = 0; ni < 8; ni++) {
        int ng = n0 + wn*64 + ni*8 + 2*lc;
        #pragma unroll
        for (int mi = 0; mi < 4; mi++) {
            int mrow = m0 + wm*64 + mi*16 + lr;
            #pragma unroll
            for (int half = 0; half < 2; half++) {
                int rr = mrow + half * 8;
                if (rr >= cnt) continue;
                *(float2*)&g_ypair[(size_t)(base + rr) * HH + ng] =
                    make_float2(acc[mi][ni][2*half], acc[mi][ni][2*half + 1]);
            }
        }
    }
}

// ---------------- final: out = x + sum_k w_k * (ypair + b2[e]) ---------------
__global__ __launch_bounds__(256) void k_final(
    const float* __restrict__ x, const float* __restrict__ b2, float* __restrict__ out)
{
    int t = blockIdx.x;
    int tid = threadIdx.x;
    int h0 = tid * 4;
    float4 r = ((const float4*)(x + (size_t)t * HH))[tid];
    #pragma unroll
    for (int k = 0; k < KK; k++) {
        int e   = g_topk_e[t*KK + k];
        float w = g_topk_w[t*KK + k];
        int s   = g_pair_slot[t*KK + k];
        float4 y  = *(const float4*)&g_ypair[(size_t)s * HH + h0];
        float4 bv = *(const float4*)&b2[e * HH + h0];
        r.x += w * (y.x + bv.x);
        r.y += w * (y.y + bv.y);
        r.z += w * (y.z + bv.z);
        r.w += w * (y.w + bv.w);
    }
    ((float4*)(out + (size_t)t * HH))[tid] = r;
}

// ---------------- launcher ---------------------------------------------------
extern "C" void kernel_launch(void* const* d_in, const int* in_sizes, int n_in,
                              void* d_out, int out_size)
{
    (void)in_sizes; (void)n_in; (void)out_size;
    const float* x      = (const float*)d_in[0];
    const float* nscale = (const float*)d_in[1];
    const float* gw     = (const float*)d_in[2];
    const float* gb     = (const float*)d_in[3];
    const float* w1     = (const float*)d_in[4];
    const float* b1     = (const float*)d_in[5];
    const float* w2     = (const float*)d_in[6];
    const float* b2     = (const float*)d_in[7];
    float* out = (float*)d_out;

    static bool attr_set = false;
    if (!attr_set) {
        cudaFuncSetAttribute(k_gemm1, cudaFuncAttributeMaxDynamicSharedMemorySize, SMEM_TOTAL);
        cudaFuncSetAttribute(k_gemm2, cudaFuncAttributeMaxDynamicSharedMemorySize, SMEM_TOTAL);
        attr_set = true;
    }

    k_zero<<<1, 32>>>();
    k_norm_gate<<<TT, 256>>>(x, nscale, gw, gb);
    k_prefix<<<1, 32>>>();
    k_route<<<(PP + 255) / 256, 256>>>();
    dim3 g1(8, 16, EE);    // 2I/256, T/128, E
    k_gemm1<<<g1, 256, SMEM_TOTAL>>>(w1, b1);
    dim3 g2(4, 16, EE);    // H/256, T/128, E
    k_gemm2<<<g2, 256, SMEM_TOTAL>>>(w2);
    k_final<<<TT, 256>>>(x, b2, out);
}